// round 8
// baseline (speedup 1.0000x reference)
#include <cuda_runtime.h>
#include <math.h>

#define B_ 2
#define C_ 10
#define N_ 100
#define M_ 50
#define HW 9216      // 96*96
#define HPWP 576     // 24*24
#define KSPLIT 72
#define KCHUNK 128   // 9216/72
#define KK 32        // k-stage in shared
#define STR 34       // row stride (floats): 8B rows, conflict-free LDS.64
#define BUF_FLOATS ((M_ + 2 * N_) * STR)   // 8500 floats per buffer
#define GRIDB 144
#define NTHR 512
#define TWO_PI_F 6.2831854820251465f
#define PI_F 3.1415927410125732f

typedef unsigned long long ull;

// ---------------- scratch ----------------
__device__ __align__(16) float g_P[B_ * N_ * HW];
__device__ __align__(16) float g_G[B_ * N_ * HW];
__device__ __align__(16) float g_Sp4[B_ * N_ * 4];
__device__ __align__(16) float g_F04[B_ * N_ * 4];
__device__ __align__(16) float g_St[B_ * M_];
// layout: [b][n][m][ks]  (ks contiguous)
__device__ __align__(16) float g_part1[B_ * N_ * M_ * KSPLIT];
__device__ __align__(16) float g_part2[B_ * N_ * M_ * KSPLIT];
__device__ unsigned g_ticket;   // monotonic ticket barrier (never reset)

__constant__ float c_w[4] = {0.625f, 0.875f, 0.125f, 0.375f};

#define FMA2(d, a, b, c) \
    asm("fma.rn.f32x2 %0, %1, %2, %3;" : "=l"(d) : "l"(a), "l"(b), "l"(c))

// ---------------- grid barrier (ticketed, wrap-safe, replay-safe) ----------
__device__ __forceinline__ void grid_barrier() {
    __syncthreads();
    __threadfence();
    if (threadIdx.x == 0) {
        unsigned ticket = atomicAdd(&g_ticket, 1u);
        unsigned target = (ticket / GRIDB + 1u) * GRIDB;
        while ((int)(*(volatile unsigned*)&g_ticket - target) < 0) {
            __nanosleep(64);
        }
    }
    __syncthreads();
    __threadfence();
}

// paired block reduce over 512 threads; valid in thread 0
__device__ __forceinline__ float2 blockReduceSum2(float a, float b, float2* sh) {
    int lane = threadIdx.x & 31;
    int wid = threadIdx.x >> 5;
    #pragma unroll
    for (int o = 16; o > 0; o >>= 1) {
        a += __shfl_down_sync(0xffffffffu, a, o);
        b += __shfl_down_sync(0xffffffffu, b, o);
    }
    if (lane == 0) sh[wid] = make_float2(a, b);
    __syncthreads();
    float2 v = (threadIdx.x < 16) ? sh[threadIdx.x] : make_float2(0.f, 0.f);
    if (wid == 0) {
        #pragma unroll
        for (int o = 8; o > 0; o >>= 1) {
            v.x += __shfl_down_sync(0xffffffffu, v.x, o);
            v.y += __shfl_down_sync(0xffffffffu, v.y, o);
        }
    }
    return v;
}

__global__ void __launch_bounds__(NTHR)
k_fused(const float* __restrict__ pred_prob,
        const float* __restrict__ pred_mask,
        const float* __restrict__ pred_mom,
        const int*   __restrict__ tcls,
        const float* __restrict__ tmask,
        const float* __restrict__ tmom,
        float* __restrict__ out) {
    extern __shared__ __align__(16) float dsm[];
    __shared__ float2 red2[16];
    int tid = threadIdx.x;
    int bi = blockIdx.x;

    // ================= phase 1: resize+derive (units 0..799) + St (800..899)
    for (int u = bi; u < 900; u += GRIDB) {
        if (u < 800) {
            int bn = u >> 2;
            int q  = u & 3;
            const float* src = pred_mask + bn * HPWP;
            for (int i = tid; i < HPWP; i += NTHR) dsm[i] = src[i];
            __syncthreads();

            float* Pout = g_P + (size_t)bn * HW + q * 2304;
            float* Gout = g_G + (size_t)bn * HW + q * 2304;
            float sp = 0.0f, sf0 = 0.0f;

            #pragma unroll
            for (int it = 0; it < 2; it++) {
                int g = tid + (it << 9);      // 0..575 groups
                if (g < 576) {
                    int y = g / 24;
                    int j = g - y * 24;
                    int yg = q * 24 + y;
                    int iy = (yg - 2) >> 2;
                    float wy = c_w[yg & 3];
                    int iy0 = max(iy, 0) * 24, iy1 = min(iy + 1, 23) * 24;
                    int cm = max(j - 1, 0), cp = min(j + 1, 23);

                    float a0 = dsm[iy0 + cm], a1 = dsm[iy0 + j], a2 = dsm[iy0 + cp];
                    float b0 = dsm[iy1 + cm], b1 = dsm[iy1 + j], b2 = dsm[iy1 + cp];

                    float t0 = a0 + 0.625f * (a1 - a0);
                    float t1 = a0 + 0.875f * (a1 - a0);
                    float t2 = a1 + 0.125f * (a2 - a1);
                    float t3 = a1 + 0.375f * (a2 - a1);
                    float u0 = b0 + 0.625f * (b1 - b0);
                    float u1 = b0 + 0.875f * (b1 - b0);
                    float u2 = b1 + 0.125f * (b2 - b1);
                    float u3 = b1 + 0.375f * (b2 - b1);

                    float pv[4];
                    pv[0] = t0 + wy * (u0 - t0);
                    pv[1] = t1 + wy * (u1 - t1);
                    pv[2] = t2 + wy * (u2 - t2);
                    pv[3] = t3 + wy * (u3 - t3);

                    float gv[4];
                    #pragma unroll
                    for (int r = 0; r < 4; r++) {
                        float p = pv[r];
                        float pc = fminf(fmaxf(p, 0.001f), 0.999f);
                        float omc = 1.0f - pc;
                        float f1 = 0.25f * (-__logf(pc)) * omc * omc;
                        float f0 = 0.75f * (-__logf(omc)) * pc * pc;
                        gv[r] = f1 - f0;
                        sp += fabsf(p);
                        sf0 += f0;
                    }
                    int o = y * 96 + j * 4;
                    *(float4*)(Pout + o) = make_float4(pv[0], pv[1], pv[2], pv[3]);
                    *(float4*)(Gout + o) = make_float4(gv[0], gv[1], gv[2], gv[3]);
                }
            }
            float2 ts = blockReduceSum2(sp, sf0, red2);
            if (tid == 0) {
                g_Sp4[bn * 4 + q] = ts.x;
                g_F04[bn * 4 + q] = ts.y;
            }
            __syncthreads();   // protect dsm reuse in next unit
        } else {
            int bm = u - 800;
            const float4* src = (const float4*)(tmask + (size_t)bm * HW);
            float s = 0.0f;
            for (int i = tid; i < HW / 4; i += NTHR) {
                float4 v = src[i];
                s += (fabsf(v.x) + fabsf(v.y)) + (fabsf(v.z) + fabsf(v.w));
            }
            float2 ts = blockReduceSum2(s, 0.0f, red2);
            if (tid == 0) g_St[bm] = ts.x;
            __syncthreads();
        }
    }

    grid_barrier();

    // ================= phase 2: dots (double-buffered FFMA2) =================
    {
        int ks = bi % KSPLIT;
        int b  = bi / KSPLIT;

        int mg = tid % 10;
        int ng = tid / 10;
        bool active = tid < 500;
        int m0 = mg * 5;
        int n0 = ng * 2;

        const float* Tbase = tmask + (size_t)b * M_ * HW;
        const float* Pbase = g_P + (size_t)b * N_ * HW;
        const float* Gbase = g_G + (size_t)b * N_ * HW;

        ull a1[5][2], a2[5][2];
        #pragma unroll
        for (int i = 0; i < 5; i++)
            #pragma unroll
            for (int j = 0; j < 2; j++) { a1[i][j] = 0ULL; a2[i][j] = 0ULL; }

        int row0 = tid >> 3, c40 = (tid & 7) << 2;
        int e1 = tid + NTHR;
        int row1 = e1 >> 3, c41 = (e1 & 7) << 2;

        float4 ft, fp0, fg0, fp1, fg1;
        int kbeg = ks * KCHUNK;

        // prefetch stage 0
        {
            int k0 = kbeg;
            if (tid < 400) ft = *(const float4*)(Tbase + (size_t)row0 * HW + k0 + c40);
            fp0 = __ldcg((const float4*)(Pbase + (size_t)row0 * HW + k0 + c40));
            fg0 = __ldcg((const float4*)(Gbase + (size_t)row0 * HW + k0 + c40));
            if (tid < 288) {
                fp1 = __ldcg((const float4*)(Pbase + (size_t)row1 * HW + k0 + c41));
                fg1 = __ldcg((const float4*)(Gbase + (size_t)row1 * HW + k0 + c41));
            }
            float* bt = dsm;
            float* bp = bt + M_ * STR;
            float* bg = bp + N_ * STR;
            if (tid < 400) {
                float* d = bt + row0 * STR + c40;
                *(float2*)(d) = make_float2(ft.x, ft.y);
                *(float2*)(d + 2) = make_float2(ft.z, ft.w);
            }
            {
                float* d = bp + row0 * STR + c40;
                *(float2*)(d) = make_float2(fp0.x, fp0.y);
                *(float2*)(d + 2) = make_float2(fp0.z, fp0.w);
                float* d2 = bg + row0 * STR + c40;
                *(float2*)(d2) = make_float2(fg0.x, fg0.y);
                *(float2*)(d2 + 2) = make_float2(fg0.z, fg0.w);
            }
            if (tid < 288) {
                float* d = bp + row1 * STR + c41;
                *(float2*)(d) = make_float2(fp1.x, fp1.y);
                *(float2*)(d + 2) = make_float2(fp1.z, fp1.w);
                float* d2 = bg + row1 * STR + c41;
                *(float2*)(d2) = make_float2(fg1.x, fg1.y);
                *(float2*)(d2 + 2) = make_float2(fg1.z, fg1.w);
            }
        }
        __syncthreads();

        #pragma unroll
        for (int s = 0; s < KCHUNK / KK; s++) {
            int cur = s & 1;
            if (s < KCHUNK / KK - 1) {
                int k0 = kbeg + (s + 1) * KK;
                if (tid < 400) ft = *(const float4*)(Tbase + (size_t)row0 * HW + k0 + c40);
                fp0 = __ldcg((const float4*)(Pbase + (size_t)row0 * HW + k0 + c40));
                fg0 = __ldcg((const float4*)(Gbase + (size_t)row0 * HW + k0 + c40));
                if (tid < 288) {
                    fp1 = __ldcg((const float4*)(Pbase + (size_t)row1 * HW + k0 + c41));
                    fg1 = __ldcg((const float4*)(Gbase + (size_t)row1 * HW + k0 + c41));
                }
            }

            {
                const float* bt = dsm + cur * BUF_FLOATS;
                const ull* sh_t2 = (const ull*)bt;
                const ull* sh_p2 = (const ull*)(bt + M_ * STR);
                const ull* sh_g2 = (const ull*)(bt + M_ * STR + N_ * STR);
                if (active) {
                    #pragma unroll
                    for (int kp = 0; kp < KK / 2; kp++) {
                        ull tv[5], pv[2], gv[2];
                        #pragma unroll
                        for (int i = 0; i < 5; i++) tv[i] = sh_t2[(m0 + i) * (STR / 2) + kp];
                        #pragma unroll
                        for (int j = 0; j < 2; j++) {
                            pv[j] = sh_p2[(n0 + j) * (STR / 2) + kp];
                            gv[j] = sh_g2[(n0 + j) * (STR / 2) + kp];
                        }
                        #pragma unroll
                        for (int i = 0; i < 5; i++) {
                            #pragma unroll
                            for (int j = 0; j < 2; j++) {
                                FMA2(a1[i][j], tv[i], pv[j], a1[i][j]);
                                FMA2(a2[i][j], tv[i], gv[j], a2[i][j]);
                            }
                        }
                    }
                }
            }

            if (s < KCHUNK / KK - 1) {
                float* bt = dsm + (cur ^ 1) * BUF_FLOATS;
                float* bp = bt + M_ * STR;
                float* bg = bp + N_ * STR;
                if (tid < 400) {
                    float* d = bt + row0 * STR + c40;
                    *(float2*)(d) = make_float2(ft.x, ft.y);
                    *(float2*)(d + 2) = make_float2(ft.z, ft.w);
                }
                {
                    float* d = bp + row0 * STR + c40;
                    *(float2*)(d) = make_float2(fp0.x, fp0.y);
                    *(float2*)(d + 2) = make_float2(fp0.z, fp0.w);
                    float* d2 = bg + row0 * STR + c40;
                    *(float2*)(d2) = make_float2(fg0.x, fg0.y);
                    *(float2*)(d2 + 2) = make_float2(fg0.z, fg0.w);
                }
                if (tid < 288) {
                    float* d = bp + row1 * STR + c41;
                    *(float2*)(d) = make_float2(fp1.x, fp1.y);
                    *(float2*)(d + 2) = make_float2(fp1.z, fp1.w);
                    float* d2 = bg + row1 * STR + c41;
                    *(float2*)(d2) = make_float2(fg1.x, fg1.y);
                    *(float2*)(d2 + 2) = make_float2(fg1.z, fg1.w);
                }
            }
            __syncthreads();
        }

        if (active) {
            #pragma unroll
            for (int i = 0; i < 5; i++) {
                #pragma unroll
                for (int j = 0; j < 2; j++) {
                    int n = n0 + j;
                    int m = m0 + i;
                    size_t idx = ((size_t)(b * N_ + n) * M_ + m) * KSPLIT + ks;
                    float2 v1 = *(float2*)&a1[i][j];
                    float2 v2 = *(float2*)&a2[i][j];
                    g_part1[idx] = v1.x + v1.y;
                    g_part2[idx] = v2.x + v2.y;
                }
            }
        }
    }

    grid_barrier();

    // ================= phase 3: assemble (2 threads per output) ==============
    {
        int gid = bi * NTHR + tid;
        int oid = gid >> 1;
        int part = gid & 1;
        bool valid = oid < B_ * N_ * M_;
        int o = valid ? oid : 0;
        int m = o % M_;
        int n = (o / M_) % N_;
        int b = o / (N_ * M_);

        size_t base = (size_t)o * KSPLIT + part * (KSPLIT / 2);
        const float4* p1 = (const float4*)(g_part1 + base);
        const float4* p2 = (const float4*)(g_part2 + base);
        float dot1 = 0.f, dot2 = 0.f;
        #pragma unroll
        for (int i = 0; i < KSPLIT / 8; i++) {
            float4 v = __ldcg(p1 + i);
            float4 w = __ldcg(p2 + i);
            dot1 += (v.x + v.y) + (v.z + v.w);
            dot2 += (w.x + w.y) + (w.z + w.w);
        }
        dot1 += __shfl_down_sync(0xffffffffu, dot1, 1);
        dot2 += __shfl_down_sync(0xffffffffu, dot2, 1);

        if (!valid || part) return;

        int cls = tcls[b * M_ + m];
        if (cls <= 0) { out[oid] = 100000.0f; return; }

        const float4 sp4 = *(const float4*)(g_Sp4 + (b * N_ + n) * 4);
        const float4 f04 = *(const float4*)(g_F04 + (b * N_ + n) * 4);
        float Sp = (sp4.x + sp4.y) + (sp4.z + sp4.w);
        float F0s = (f04.x + f04.y) + (f04.z + f04.w);
        float St = g_St[b * M_ + m];
        float pos = Sp + St;
        float cost_dice = 1.0f - 2.0f * dot1 / (pos + 0.001f);
        float cost_focal = (F0s + dot2) * (1.0f / (float)HW);
        float cost_class = -pred_prob[((size_t)b * C_ + cls) * N_ + n];

        const float* pmv = pred_mom + (size_t)(b * N_ + n) * 4;
        float p0 = __expf(fminf(pmv[0], 10.0f));
        float p1f = TWO_PI_F / (1.0f + __expf(-pmv[1]));
        float p2f = TWO_PI_F / (1.0f + __expf(-pmv[2]));
        float p3 = __expf(fminf(pmv[3], 10.0f));
        const float* tmv = tmom + (size_t)(b * M_ + m) * 4;
        float t0 = tmv[0], t1 = tmv[1], t2 = tmv[2], t3 = tmv[3];

        float pe = (t2 - p2f > PI_F) ? TWO_PI_F : 0.0f;
        float te = (p2f - t2 > PI_F) ? TWO_PI_F : 0.0f;
        float l1 = (fabsf(p0 / (t0 + 0.001f) - 1.0f)
                  + fabsf(p1f / (t1 + 0.001f) - 1.0f)
                  + fabsf((p2f + pe) / (t2 + te + 0.001f) - 1.0f)
                  + fabsf(p3 / (t3 + 0.001f) - 1.0f)) * 0.25f;

        float w1 = p0, x1 = p1f, y1 = p2f, h1 = p3;
        float w2 = t0, x2 = t1, y2 = t2, h2 = t3;
        float y1e = (y2 - y1 > PI_F) ? TWO_PI_F : 0.0f;
        float y2e = (y1 - y2 > PI_F) ? TWO_PI_F : 0.0f;
        y1 += y1e;
        y2 += y2e;
        float r1 = x1 + w1 * 0.5f, l1b = x1 - w1 * 0.5f;
        float r2 = x2 + w2 * 0.5f, l2b = x2 - w2 * 0.5f;
        float u1 = y1 + h1 * 0.5f, d1 = y1 - h1 * 0.5f;
        float u2 = y2 + h2 * 0.5f, d2 = y2 - h2 * 0.5f;
        float w = fminf(r1, r2) - fmaxf(l1b, l2b);
        float h = fminf(u1, u2) - fmaxf(d1, d2);
        float iou = (w > 0.0f && h > 0.0f)
                    ? (w * h) / (w1 * h1 + w2 * h2 - w * h + 0.001f) : 0.0f;
        float cw = fmaxf(r1, r2) - fminf(l1b, l2b);
        float ch = fmaxf(u1, u2) - fminf(d1, d2);
        float cw2 = cw * cw, ch2 = ch * ch;
        float dw = w1 - w2, dh = h1 - h2;
        float rho_w = dw * dw / (cw2 + 0.001f);
        float rho_h = dh * dh / (ch2 + 0.001f);
        float dx = x1 - x2, dy = y1 - y2;
        float rho_d = (dx * dx + dy * dy) / (cw2 + ch2 + 0.001f);
        float ce = 1.0f - iou + rho_d + rho_w + rho_h;

        out[oid] = 0.25f * cost_focal + 0.75f * cost_dice + cost_class
                 + 0.8f * l1 + 0.2f * ce;
    }
}

extern "C" void kernel_launch(void* const* d_in, const int* in_sizes, int n_in,
                              void* d_out, int out_size) {
    const float* pred_prob = (const float*)d_in[0];
    const float* pred_mask = (const float*)d_in[1];
    const float* pred_mom  = (const float*)d_in[2];
    const int*   tcls      = (const int*)d_in[3];
    const float* tmask     = (const float*)d_in[4];
    const float* tmom      = (const float*)d_in[5];
    float* out = (float*)d_out;

    int smem = 2 * BUF_FLOATS * sizeof(float);  // 68000 B
    static int configured = 0;
    if (!configured) {
        cudaFuncSetAttribute(k_fused, cudaFuncAttributeMaxDynamicSharedMemorySize, smem);
        configured = 1;
    }
    k_fused<<<GRIDB, NTHR, smem>>>(pred_prob, pred_mask, pred_mom, tcls, tmask, tmom, out);
}

// round 9
// speedup vs baseline: 1.3234x; 1.3234x over previous
#include <cuda_runtime.h>
#include <math.h>

#define B_ 2
#define C_ 10
#define N_ 100
#define M_ 50
#define HW 9216      // 96*96
#define HPWP 576     // 24*24
#define KSPLIT 72
#define KCHUNK 128   // 9216/72
#define KK 32
#define STR 34       // tile row stride (floats)
#define T_FLOATS (M_ * STR)             // 1700
#define PG_FLOATS (N_ * STR)            // 3400
#define BUF_FLOATS (T_FLOATS + 2 * PG_FLOATS)  // 8500
#define SRC_FLOATS (4 * N_ * 24)        // 9600
#define DSMEM_BYTES ((SRC_FLOATS + 2 * BUF_FLOATS) * 4)  // 106400
#define TWO_PI_F 6.2831854820251465f
#define PI_F 3.1415927410125732f

typedef unsigned long long ull;

// ---------------- scratch ----------------
__device__ __align__(16) float g_Sp[B_ * N_];
__device__ __align__(16) float g_St[B_ * M_];
__device__ __align__(16) float g_f0Part[B_ * N_ * KSPLIT];
// layout: [b][n][m][ks]
__device__ __align__(16) float g_part1[B_ * N_ * M_ * KSPLIT];
__device__ __align__(16) float g_part2[B_ * N_ * M_ * KSPLIT];

__constant__ float c_w[4] = {0.625f, 0.875f, 0.125f, 0.375f};

#define FMA2(d, a, b, c) \
    asm("fma.rn.f32x2 %0, %1, %2, %3;" : "=l"(d) : "l"(a), "l"(b), "l"(c))

// ---------------- helpers ----------------
__device__ __forceinline__ float blockReduceSum(float v, float* sh) {
    int lane = threadIdx.x & 31;
    int wid = threadIdx.x >> 5;
    #pragma unroll
    for (int o = 16; o > 0; o >>= 1) v += __shfl_down_sync(0xffffffffu, v, o);
    if (lane == 0) sh[wid] = v;
    __syncthreads();
    v = (threadIdx.x < 8) ? sh[threadIdx.x] : 0.0f;
    if (wid == 0) {
        #pragma unroll
        for (int o = 4; o > 0; o >>= 1) v += __shfl_down_sync(0xffffffffu, v, o);
    }
    return v;
}

// 4-px conversion group: bilinear + focal terms; returns f0 partial sum.
__device__ __forceinline__ float conv_group(const float* __restrict__ S0,
                                            const float* __restrict__ S1,
                                            int j, float wy,
                                            float* Pd, float* Gd) {
    int cm = max(j - 1, 0), cp = min(j + 1, 23);
    float a0 = S0[cm], a1 = S0[j], a2 = S0[cp];
    float b0 = S1[cm], b1 = S1[j], b2 = S1[cp];
    float t0 = a0 + 0.625f * (a1 - a0);
    float t1 = a0 + 0.875f * (a1 - a0);
    float t2 = a1 + 0.125f * (a2 - a1);
    float t3 = a1 + 0.375f * (a2 - a1);
    float u0 = b0 + 0.625f * (b1 - b0);
    float u1 = b0 + 0.875f * (b1 - b0);
    float u2 = b1 + 0.125f * (b2 - b1);
    float u3 = b1 + 0.375f * (b2 - b1);
    float pv[4];
    pv[0] = t0 + wy * (u0 - t0);
    pv[1] = t1 + wy * (u1 - t1);
    pv[2] = t2 + wy * (u2 - t2);
    pv[3] = t3 + wy * (u3 - t3);
    float gv[4];
    float f0s = 0.0f;
    #pragma unroll
    for (int r = 0; r < 4; r++) {
        float pc = fminf(fmaxf(pv[r], 0.001f), 0.999f);
        float omc = 1.0f - pc;
        float f1 = 0.25f * (-__logf(pc)) * omc * omc;
        float f0 = 0.75f * (-__logf(omc)) * pc * pc;
        gv[r] = f1 - f0;
        f0s += f0;
    }
    *(float2*)(Pd)     = make_float2(pv[0], pv[1]);
    *(float2*)(Pd + 2) = make_float2(pv[2], pv[3]);
    *(float2*)(Gd)     = make_float2(gv[0], gv[1]);
    *(float2*)(Gd + 2) = make_float2(gv[2], gv[3]);
    return f0s;
}

// ------ kernel 1: St (blocks 0..99) + analytic Sp (blocks 100..299) ------
__global__ void k_st(const float* __restrict__ tmask,
                     const float* __restrict__ pred_mask) {
    __shared__ float red[8];
    int tid = threadIdx.x;
    if (blockIdx.x < 100) {
        int bm = blockIdx.x;
        const float4* src = (const float4*)(tmask + (size_t)bm * HW);
        float s = 0.0f;
        for (int i = tid; i < HW / 4; i += 256) {
            float4 v = src[i];
            s += (fabsf(v.x) + fabsf(v.y)) + (fabsf(v.z) + fabsf(v.w));
        }
        float t = blockReduceSum(s, red);
        if (tid == 0) g_St[bm] = t;
    } else {
        int bn = blockIdx.x - 100;   // 0..199
        const float4* src = (const float4*)(pred_mask + (size_t)bn * HPWP);
        float s = 0.0f;
        if (tid < HPWP / 4) {
            float4 v = src[tid];
            s = (v.x + v.y) + (v.z + v.w);
        }
        float t = blockReduceSum(s, red);
        if (tid == 0) g_Sp[bn] = 16.0f * t;   // uniform bilinear weight
    }
}

// ------ kernel 2: dots with fused on-the-fly resize+convert ------
__global__ void __launch_bounds__(512) k_dots(const float* __restrict__ tmask,
                                              const float* __restrict__ pred_mask) {
    extern __shared__ __align__(16) float dsm[];
    int ks = blockIdx.x;
    int b  = blockIdx.y;
    int tid = threadIdx.x;

    int mg = tid % 10;
    int ng = tid / 10;
    bool active = tid < 500;
    int m0 = mg * 5;
    int n0 = ng * 2;

    const float* Tbase = tmask + (size_t)b * M_ * HW;
    const float* Mbase = pred_mask + (size_t)b * N_ * HPWP;

    int kbeg = ks * KCHUNK;
    int yg0 = kbeg / 96;

    // ---- prologue: load 4 source rows for all 100 n ----
    {
        int iyA = (yg0 - 2) >> 2;
        int iyB = (yg0 - 1) >> 2;   // for yg0+1
        int rows4[4];
        rows4[0] = max(iyA, 0);
        rows4[1] = min(iyA + 1, 23);
        rows4[2] = max(iyB, 0);
        rows4[3] = min(iyB + 1, 23);
        for (int e = tid; e < 2400; e += 512) {
            int slot = e / 600;
            int rem = e - slot * 600;
            int n = rem / 6;
            int c4 = (rem - n * 6) << 2;
            float4 v = *(const float4*)(Mbase + (size_t)n * HPWP + rows4[slot] * 24 + c4);
            *(float4*)(dsm + slot * 2400 + n * 24 + c4) = v;
        }
    }

    int row0 = tid >> 3, c40 = (tid & 7) << 2;
    float4 ft;
    if (tid < 400) ft = *(const float4*)(Tbase + (size_t)row0 * HW + kbeg + c40);
    __syncthreads();   // source rows ready

    float f0acc0 = 0.0f, f0acc1 = 0.0f;

    // ---- convert stage 0 into buffer 0 ----
    {
        int jb = (kbeg - yg0 * 96) >> 2;
        float wy = c_w[yg0 & 3];
        float* buf0 = dsm + SRC_FLOATS;
        {
            int n = tid >> 3, gx = tid & 7;
            const float* S0 = dsm + n * 24;
            float* Pd = buf0 + T_FLOATS + n * STR + (gx << 2);
            f0acc0 += conv_group(S0, S0 + 2400, jb + gx, wy, Pd, Pd + PG_FLOATS);
        }
        if (tid < 288) {
            int n = (tid >> 3) + 64, gx = tid & 7;
            const float* S0 = dsm + n * 24;
            float* Pd = buf0 + T_FLOATS + n * STR + (gx << 2);
            f0acc1 += conv_group(S0, S0 + 2400, jb + gx, wy, Pd, Pd + PG_FLOATS);
        }
        if (tid < 400) {
            float* d = buf0 + row0 * STR + c40;
            *(float2*)(d)     = make_float2(ft.x, ft.y);
            *(float2*)(d + 2) = make_float2(ft.z, ft.w);
        }
    }
    __syncthreads();

    ull a1[5][2], a2[5][2];
    #pragma unroll
    for (int i = 0; i < 5; i++)
        #pragma unroll
        for (int j = 0; j < 2; j++) { a1[i][j] = 0ULL; a2[i][j] = 0ULL; }

    for (int s = 0; s < 4; s++) {
        int cur = s & 1;
        float* bufn = dsm + SRC_FLOATS + (cur ^ 1) * BUF_FLOATS;

        if (s < 3) {
            int k0n = kbeg + ((s + 1) << 5);
            if (tid < 400) ft = *(const float4*)(Tbase + (size_t)row0 * HW + k0n + c40);
            int yg = k0n / 96;
            const float* Sb = dsm + ((yg == yg0) ? 0 : 4800);
            float wy = c_w[yg & 3];
            int jb = (k0n - yg * 96) >> 2;
            {
                int n = tid >> 3, gx = tid & 7;
                const float* S0 = Sb + n * 24;
                float* Pd = bufn + T_FLOATS + n * STR + (gx << 2);
                f0acc0 += conv_group(S0, S0 + 2400, jb + gx, wy, Pd, Pd + PG_FLOATS);
            }
            if (tid < 288) {
                int n = (tid >> 3) + 64, gx = tid & 7;
                const float* S0 = Sb + n * 24;
                float* Pd = bufn + T_FLOATS + n * STR + (gx << 2);
                f0acc1 += conv_group(S0, S0 + 2400, jb + gx, wy, Pd, Pd + PG_FLOATS);
            }
        }

        // FMA phase on current buffer
        {
            const float* bt = dsm + SRC_FLOATS + cur * BUF_FLOATS;
            const ull* sh_t2 = (const ull*)bt;
            const ull* sh_p2 = (const ull*)(bt + T_FLOATS);
            const ull* sh_g2 = (const ull*)(bt + T_FLOATS + PG_FLOATS);
            if (active) {
                #pragma unroll
                for (int kp = 0; kp < KK / 2; kp++) {
                    ull tv[5], pv[2], gv[2];
                    #pragma unroll
                    for (int i = 0; i < 5; i++) tv[i] = sh_t2[(m0 + i) * (STR / 2) + kp];
                    #pragma unroll
                    for (int j = 0; j < 2; j++) {
                        pv[j] = sh_p2[(n0 + j) * (STR / 2) + kp];
                        gv[j] = sh_g2[(n0 + j) * (STR / 2) + kp];
                    }
                    #pragma unroll
                    for (int i = 0; i < 5; i++) {
                        #pragma unroll
                        for (int j = 0; j < 2; j++) {
                            FMA2(a1[i][j], tv[i], pv[j], a1[i][j]);
                            FMA2(a2[i][j], tv[i], gv[j], a2[i][j]);
                        }
                    }
                }
            }
        }

        if (s < 3 && tid < 400) {
            float* d = bufn + row0 * STR + c40;
            *(float2*)(d)     = make_float2(ft.x, ft.y);
            *(float2*)(d + 2) = make_float2(ft.z, ft.w);
        }
        __syncthreads();
    }

    // ---- epilogue: dot partials ----
    if (active) {
        #pragma unroll
        for (int i = 0; i < 5; i++) {
            #pragma unroll
            for (int j = 0; j < 2; j++) {
                int n = n0 + j;
                int m = m0 + i;
                size_t idx = ((size_t)(b * N_ + n) * M_ + m) * KSPLIT + ks;
                float2 v1 = *(float2*)&a1[i][j];
                float2 v2 = *(float2*)&a2[i][j];
                g_part1[idx] = v1.x + v1.y;
                g_part2[idx] = v2.x + v2.y;
            }
        }
    }

    // ---- f0 partials: oct-reduce (8 gx lanes per n) ----
    f0acc0 += __shfl_down_sync(0xffffffffu, f0acc0, 4, 8);
    f0acc0 += __shfl_down_sync(0xffffffffu, f0acc0, 2, 8);
    f0acc0 += __shfl_down_sync(0xffffffffu, f0acc0, 1, 8);
    f0acc1 += __shfl_down_sync(0xffffffffu, f0acc1, 4, 8);
    f0acc1 += __shfl_down_sync(0xffffffffu, f0acc1, 2, 8);
    f0acc1 += __shfl_down_sync(0xffffffffu, f0acc1, 1, 8);
    if ((tid & 7) == 0) {
        int n = tid >> 3;
        g_f0Part[((size_t)(b * N_ + n)) * KSPLIT + ks] = f0acc0;
        if (tid < 288)
            g_f0Part[((size_t)(b * N_ + n + 64)) * KSPLIT + ks] = f0acc1;
    }
}

// ------ kernel 3: assemble (2 threads per output) ------
__global__ void k_assemble(const float* __restrict__ pred_prob,
                           const float* __restrict__ pred_mom,
                           const int*   __restrict__ tcls,
                           const float* __restrict__ tmom,
                           float* __restrict__ out) {
    int gid = blockIdx.x * blockDim.x + threadIdx.x;
    int oid = gid >> 1;
    int part = gid & 1;
    bool valid = oid < B_ * N_ * M_;
    int o = valid ? oid : 0;
    int m = o % M_;
    int n = (o / M_) % N_;
    int b = o / (N_ * M_);

    size_t base = (size_t)o * KSPLIT + part * (KSPLIT / 2);
    const float4* p1 = (const float4*)(g_part1 + base);
    const float4* p2 = (const float4*)(g_part2 + base);
    size_t fb = ((size_t)(b * N_ + n)) * KSPLIT + part * (KSPLIT / 2);
    const float4* pf = (const float4*)(g_f0Part + fb);
    float dot1 = 0.f, dot2 = 0.f, f0s = 0.f;
    #pragma unroll
    for (int i = 0; i < KSPLIT / 8; i++) {
        float4 v = p1[i];
        float4 w = p2[i];
        float4 x = pf[i];
        dot1 += (v.x + v.y) + (v.z + v.w);
        dot2 += (w.x + w.y) + (w.z + w.w);
        f0s  += (x.x + x.y) + (x.z + x.w);
    }
    dot1 += __shfl_down_sync(0xffffffffu, dot1, 1);
    dot2 += __shfl_down_sync(0xffffffffu, dot2, 1);
    f0s  += __shfl_down_sync(0xffffffffu, f0s, 1);

    if (!valid || part) return;

    int cls = tcls[b * M_ + m];
    if (cls <= 0) { out[oid] = 100000.0f; return; }

    float Sp = g_Sp[b * N_ + n];
    float St = g_St[b * M_ + m];
    float pos = Sp + St;
    float cost_dice = 1.0f - 2.0f * dot1 / (pos + 0.001f);
    float cost_focal = (f0s + dot2) * (1.0f / (float)HW);
    float cost_class = -pred_prob[((size_t)b * C_ + cls) * N_ + n];

    const float* pmv = pred_mom + (size_t)(b * N_ + n) * 4;
    float p0 = __expf(fminf(pmv[0], 10.0f));
    float p1f = TWO_PI_F / (1.0f + __expf(-pmv[1]));
    float p2f = TWO_PI_F / (1.0f + __expf(-pmv[2]));
    float p3 = __expf(fminf(pmv[3], 10.0f));
    const float* tmv = tmom + (size_t)(b * M_ + m) * 4;
    float t0 = tmv[0], t1 = tmv[1], t2 = tmv[2], t3 = tmv[3];

    float pe = (t2 - p2f > PI_F) ? TWO_PI_F : 0.0f;
    float te = (p2f - t2 > PI_F) ? TWO_PI_F : 0.0f;
    float l1 = (fabsf(p0 / (t0 + 0.001f) - 1.0f)
              + fabsf(p1f / (t1 + 0.001f) - 1.0f)
              + fabsf((p2f + pe) / (t2 + te + 0.001f) - 1.0f)
              + fabsf(p3 / (t3 + 0.001f) - 1.0f)) * 0.25f;

    float w1 = p0, x1 = p1f, y1 = p2f, h1 = p3;
    float w2 = t0, x2 = t1, y2 = t2, h2 = t3;
    float y1e = (y2 - y1 > PI_F) ? TWO_PI_F : 0.0f;
    float y2e = (y1 - y2 > PI_F) ? TWO_PI_F : 0.0f;
    y1 += y1e;
    y2 += y2e;
    float r1 = x1 + w1 * 0.5f, l1b = x1 - w1 * 0.5f;
    float r2 = x2 + w2 * 0.5f, l2b = x2 - w2 * 0.5f;
    float u1 = y1 + h1 * 0.5f, d1 = y1 - h1 * 0.5f;
    float u2 = y2 + h2 * 0.5f, d2 = y2 - h2 * 0.5f;
    float w = fminf(r1, r2) - fmaxf(l1b, l2b);
    float h = fminf(u1, u2) - fmaxf(d1, d2);
    float iou = (w > 0.0f && h > 0.0f)
                ? (w * h) / (w1 * h1 + w2 * h2 - w * h + 0.001f) : 0.0f;
    float cw = fmaxf(r1, r2) - fminf(l1b, l2b);
    float ch = fmaxf(u1, u2) - fminf(d1, d2);
    float cw2 = cw * cw, ch2 = ch * ch;
    float dw = w1 - w2, dh = h1 - h2;
    float rho_w = dw * dw / (cw2 + 0.001f);
    float rho_h = dh * dh / (ch2 + 0.001f);
    float dx = x1 - x2, dy = y1 - y2;
    float rho_d = (dx * dx + dy * dy) / (cw2 + ch2 + 0.001f);
    float ce = 1.0f - iou + rho_d + rho_w + rho_h;

    out[oid] = 0.25f * cost_focal + 0.75f * cost_dice + cost_class
             + 0.8f * l1 + 0.2f * ce;
}

extern "C" void kernel_launch(void* const* d_in, const int* in_sizes, int n_in,
                              void* d_out, int out_size) {
    const float* pred_prob = (const float*)d_in[0];
    const float* pred_mask = (const float*)d_in[1];
    const float* pred_mom  = (const float*)d_in[2];
    const int*   tcls      = (const int*)d_in[3];
    const float* tmask     = (const float*)d_in[4];
    const float* tmom      = (const float*)d_in[5];
    float* out = (float*)d_out;

    static int configured = 0;
    if (!configured) {
        cudaFuncSetAttribute(k_dots, cudaFuncAttributeMaxDynamicSharedMemorySize,
                             DSMEM_BYTES);
        configured = 1;
    }

    k_st<<<300, 256>>>(tmask, pred_mask);
    dim3 grid(KSPLIT, B_);
    k_dots<<<grid, 512, DSMEM_BYTES>>>(tmask, pred_mask);
    int total_threads = 2 * B_ * N_ * M_;
    k_assemble<<<(total_threads + 255) / 256, 256>>>(pred_prob, pred_mom, tcls, tmom, out);
}

// round 10
// speedup vs baseline: 1.3480x; 1.0186x over previous
#include <cuda_runtime.h>
#include <math.h>

#define B_ 2
#define C_ 10
#define N_ 100
#define M_ 50
#define HW 9216      // 96*96
#define HPWP 576     // 24*24
#define KSPLIT 72
#define KCHUNK 128   // 9216/72
#define KK 32
#define STR 34       // tile row stride (floats)
#define T_FLOATS (M_ * STR)             // 1700
#define PG_FLOATS (N_ * STR)            // 3400
#define BUF_FLOATS (T_FLOATS + 2 * PG_FLOATS)  // 8500
#define SRC_FLOATS (4 * N_ * 24)        // 9600
#define DSMEM_BYTES ((SRC_FLOATS + 2 * BUF_FLOATS) * 4)  // 106400
#define TWO_PI_F 6.2831854820251465f
#define PI_F 3.1415927410125732f

typedef unsigned long long ull;

// ---------------- scratch ----------------
__device__ __align__(16) float g_Sp[B_ * N_];
__device__ __align__(16) float g_f0Part[B_ * N_ * KSPLIT];
__device__ __align__(16) float g_stPart[B_ * M_ * KSPLIT];
// layout: [b][n][m][ks]
__device__ __align__(16) float g_part1[B_ * N_ * M_ * KSPLIT];
__device__ __align__(16) float g_part2[B_ * N_ * M_ * KSPLIT];

__constant__ float c_w[4] = {0.625f, 0.875f, 0.125f, 0.375f};

#define FMA2(d, a, b, c) \
    asm("fma.rn.f32x2 %0, %1, %2, %3;" : "=l"(d) : "l"(a), "l"(b), "l"(c))

// ---------------- helpers ----------------
__device__ __forceinline__ float blockReduceSum(float v, float* sh) {
    int lane = threadIdx.x & 31;
    int wid = threadIdx.x >> 5;
    #pragma unroll
    for (int o = 16; o > 0; o >>= 1) v += __shfl_down_sync(0xffffffffu, v, o);
    if (lane == 0) sh[wid] = v;
    __syncthreads();
    v = (threadIdx.x < 8) ? sh[threadIdx.x] : 0.0f;
    if (wid == 0) {
        #pragma unroll
        for (int o = 4; o > 0; o >>= 1) v += __shfl_down_sync(0xffffffffu, v, o);
    }
    return v;
}

// 4-px conversion group: bilinear + focal terms; returns f0 partial sum.
__device__ __forceinline__ float conv_group(const float* __restrict__ S0,
                                            const float* __restrict__ S1,
                                            int j, float wy,
                                            float* Pd, float* Gd) {
    int cm = max(j - 1, 0), cp = min(j + 1, 23);
    float a0 = S0[cm], a1 = S0[j], a2 = S0[cp];
    float b0 = S1[cm], b1 = S1[j], b2 = S1[cp];
    float t0 = a0 + 0.625f * (a1 - a0);
    float t1 = a0 + 0.875f * (a1 - a0);
    float t2 = a1 + 0.125f * (a2 - a1);
    float t3 = a1 + 0.375f * (a2 - a1);
    float u0 = b0 + 0.625f * (b1 - b0);
    float u1 = b0 + 0.875f * (b1 - b0);
    float u2 = b1 + 0.125f * (b2 - b1);
    float u3 = b1 + 0.375f * (b2 - b1);
    float pv[4];
    pv[0] = t0 + wy * (u0 - t0);
    pv[1] = t1 + wy * (u1 - t1);
    pv[2] = t2 + wy * (u2 - t2);
    pv[3] = t3 + wy * (u3 - t3);
    float gv[4];
    float f0s = 0.0f;
    #pragma unroll
    for (int r = 0; r < 4; r++) {
        float pc = fminf(fmaxf(pv[r], 0.001f), 0.999f);
        float omc = 1.0f - pc;
        float f1 = 0.25f * (-__logf(pc)) * omc * omc;
        float f0 = 0.75f * (-__logf(omc)) * pc * pc;
        gv[r] = f1 - f0;
        f0s += f0;
    }
    *(float2*)(Pd)     = make_float2(pv[0], pv[1]);
    *(float2*)(Pd + 2) = make_float2(pv[2], pv[3]);
    *(float2*)(Gd)     = make_float2(gv[0], gv[1]);
    *(float2*)(Gd + 2) = make_float2(gv[2], gv[3]);
    return f0s;
}

// ------ kernel 1: analytic Sp only (tiny) ------
__global__ void k_sp(const float* __restrict__ pred_mask) {
    __shared__ float red[8];
    int bn = blockIdx.x;   // 0..199
    const float4* src = (const float4*)(pred_mask + (size_t)bn * HPWP);
    float s = 0.0f;
    if (threadIdx.x < HPWP / 4) {
        float4 v = src[threadIdx.x];
        s = (v.x + v.y) + (v.z + v.w);
    }
    float t = blockReduceSum(s, red);
    if (threadIdx.x == 0) g_Sp[bn] = 16.0f * t;   // uniform bilinear weight
}

// ------ kernel 2: dots with fused resize/convert + St partials ------
__global__ void __launch_bounds__(512) k_dots(const float* __restrict__ tmask,
                                              const float* __restrict__ pred_mask) {
    extern __shared__ __align__(16) float dsm[];
    int ks = blockIdx.x;
    int b  = blockIdx.y;
    int tid = threadIdx.x;

    int mg = tid % 10;
    int ng = tid / 10;
    bool active = tid < 500;
    int m0 = mg * 5;
    int n0 = ng * 2;

    const float* Tbase = tmask + (size_t)b * M_ * HW;
    const float* Mbase = pred_mask + (size_t)b * N_ * HPWP;

    int kbeg = ks * KCHUNK;
    int yg0 = kbeg / 96;

    // ---- prologue: load 4 source rows for all 100 n ----
    {
        int iyA = (yg0 - 2) >> 2;
        int iyB = (yg0 - 1) >> 2;   // for yg0+1
        int rows4[4];
        rows4[0] = max(iyA, 0);
        rows4[1] = min(iyA + 1, 23);
        rows4[2] = max(iyB, 0);
        rows4[3] = min(iyB + 1, 23);
        for (int e = tid; e < 2400; e += 512) {
            int slot = e / 600;
            int rem = e - slot * 600;
            int n = rem / 6;
            int c4 = (rem - n * 6) << 2;
            float4 v = *(const float4*)(Mbase + (size_t)n * HPWP + rows4[slot] * 24 + c4);
            *(float4*)(dsm + slot * 2400 + n * 24 + c4) = v;
        }
    }

    int row0 = tid >> 3, c40 = (tid & 7) << 2;
    float st_acc = 0.0f;
    float4 ft;
    if (tid < 400) {
        ft = *(const float4*)(Tbase + (size_t)row0 * HW + kbeg + c40);
        st_acc += (fabsf(ft.x) + fabsf(ft.y)) + (fabsf(ft.z) + fabsf(ft.w));
    }
    __syncthreads();   // source rows ready

    float f0acc0 = 0.0f, f0acc1 = 0.0f;

    // ---- convert stage 0 into buffer 0 ----
    {
        int jb = (kbeg - yg0 * 96) >> 2;
        float wy = c_w[yg0 & 3];
        float* buf0 = dsm + SRC_FLOATS;
        {
            int n = tid >> 3, gx = tid & 7;
            const float* S0 = dsm + n * 24;
            float* Pd = buf0 + T_FLOATS + n * STR + (gx << 2);
            f0acc0 += conv_group(S0, S0 + 2400, jb + gx, wy, Pd, Pd + PG_FLOATS);
        }
        if (tid < 288) {
            int n = (tid >> 3) + 64, gx = tid & 7;
            const float* S0 = dsm + n * 24;
            float* Pd = buf0 + T_FLOATS + n * STR + (gx << 2);
            f0acc1 += conv_group(S0, S0 + 2400, jb + gx, wy, Pd, Pd + PG_FLOATS);
        }
        if (tid < 400) {
            float* d = buf0 + row0 * STR + c40;
            *(float2*)(d)     = make_float2(ft.x, ft.y);
            *(float2*)(d + 2) = make_float2(ft.z, ft.w);
        }
    }
    __syncthreads();

    ull a1[5][2], a2[5][2];
    #pragma unroll
    for (int i = 0; i < 5; i++)
        #pragma unroll
        for (int j = 0; j < 2; j++) { a1[i][j] = 0ULL; a2[i][j] = 0ULL; }

    for (int s = 0; s < 4; s++) {
        int cur = s & 1;
        float* bufn = dsm + SRC_FLOATS + (cur ^ 1) * BUF_FLOATS;

        if (s < 3) {
            int k0n = kbeg + ((s + 1) << 5);
            if (tid < 400) {
                ft = *(const float4*)(Tbase + (size_t)row0 * HW + k0n + c40);
                st_acc += (fabsf(ft.x) + fabsf(ft.y)) + (fabsf(ft.z) + fabsf(ft.w));
            }
            int yg = k0n / 96;
            const float* Sb = dsm + ((yg == yg0) ? 0 : 4800);
            float wy = c_w[yg & 3];
            int jb = (k0n - yg * 96) >> 2;
            {
                int n = tid >> 3, gx = tid & 7;
                const float* S0 = Sb + n * 24;
                float* Pd = bufn + T_FLOATS + n * STR + (gx << 2);
                f0acc0 += conv_group(S0, S0 + 2400, jb + gx, wy, Pd, Pd + PG_FLOATS);
            }
            if (tid < 288) {
                int n = (tid >> 3) + 64, gx = tid & 7;
                const float* S0 = Sb + n * 24;
                float* Pd = bufn + T_FLOATS + n * STR + (gx << 2);
                f0acc1 += conv_group(S0, S0 + 2400, jb + gx, wy, Pd, Pd + PG_FLOATS);
            }
        }

        // FMA phase on current buffer
        {
            const float* bt = dsm + SRC_FLOATS + cur * BUF_FLOATS;
            const ull* sh_t2 = (const ull*)bt;
            const ull* sh_p2 = (const ull*)(bt + T_FLOATS);
            const ull* sh_g2 = (const ull*)(bt + T_FLOATS + PG_FLOATS);
            if (active) {
                #pragma unroll
                for (int kp = 0; kp < KK / 2; kp++) {
                    ull tv[5], pv[2], gv[2];
                    #pragma unroll
                    for (int i = 0; i < 5; i++) tv[i] = sh_t2[(m0 + i) * (STR / 2) + kp];
                    #pragma unroll
                    for (int j = 0; j < 2; j++) {
                        pv[j] = sh_p2[(n0 + j) * (STR / 2) + kp];
                        gv[j] = sh_g2[(n0 + j) * (STR / 2) + kp];
                    }
                    #pragma unroll
                    for (int i = 0; i < 5; i++) {
                        #pragma unroll
                        for (int j = 0; j < 2; j++) {
                            FMA2(a1[i][j], tv[i], pv[j], a1[i][j]);
                            FMA2(a2[i][j], tv[i], gv[j], a2[i][j]);
                        }
                    }
                }
            }
        }

        if (s < 3 && tid < 400) {
            float* d = bufn + row0 * STR + c40;
            *(float2*)(d)     = make_float2(ft.x, ft.y);
            *(float2*)(d + 2) = make_float2(ft.z, ft.w);
        }
        __syncthreads();
    }

    // ---- epilogue: dot partials ----
    if (active) {
        #pragma unroll
        for (int i = 0; i < 5; i++) {
            #pragma unroll
            for (int j = 0; j < 2; j++) {
                int n = n0 + j;
                int m = m0 + i;
                size_t idx = ((size_t)(b * N_ + n) * M_ + m) * KSPLIT + ks;
                float2 v1 = *(float2*)&a1[i][j];
                float2 v2 = *(float2*)&a2[i][j];
                g_part1[idx] = v1.x + v1.y;
                g_part2[idx] = v2.x + v2.y;
            }
        }
    }

    // ---- f0 + st partials: oct-reduce (8 lanes per row) ----
    f0acc0 += __shfl_down_sync(0xffffffffu, f0acc0, 4, 8);
    f0acc0 += __shfl_down_sync(0xffffffffu, f0acc0, 2, 8);
    f0acc0 += __shfl_down_sync(0xffffffffu, f0acc0, 1, 8);
    f0acc1 += __shfl_down_sync(0xffffffffu, f0acc1, 4, 8);
    f0acc1 += __shfl_down_sync(0xffffffffu, f0acc1, 2, 8);
    f0acc1 += __shfl_down_sync(0xffffffffu, f0acc1, 1, 8);
    st_acc += __shfl_down_sync(0xffffffffu, st_acc, 4, 8);
    st_acc += __shfl_down_sync(0xffffffffu, st_acc, 2, 8);
    st_acc += __shfl_down_sync(0xffffffffu, st_acc, 1, 8);
    if ((tid & 7) == 0) {
        int n = tid >> 3;
        g_f0Part[((size_t)(b * N_ + n)) * KSPLIT + ks] = f0acc0;
        if (tid < 288)
            g_f0Part[((size_t)(b * N_ + n + 64)) * KSPLIT + ks] = f0acc1;
        if (tid < 400)
            g_stPart[((size_t)(b * M_ + n)) * KSPLIT + ks] = st_acc;  // n==row0 here
    }
}

// ------ kernel 3: assemble (2 threads per output) ------
__global__ void k_assemble(const float* __restrict__ pred_prob,
                           const float* __restrict__ pred_mom,
                           const int*   __restrict__ tcls,
                           const float* __restrict__ tmom,
                           float* __restrict__ out) {
    int gid = blockIdx.x * blockDim.x + threadIdx.x;
    int oid = gid >> 1;
    int part = gid & 1;
    bool valid = oid < B_ * N_ * M_;
    int o = valid ? oid : 0;
    int m = o % M_;
    int n = (o / M_) % N_;
    int b = o / (N_ * M_);

    size_t base = (size_t)o * KSPLIT + part * (KSPLIT / 2);
    const float4* p1 = (const float4*)(g_part1 + base);
    const float4* p2 = (const float4*)(g_part2 + base);
    size_t fb = ((size_t)(b * N_ + n)) * KSPLIT + part * (KSPLIT / 2);
    const float4* pf = (const float4*)(g_f0Part + fb);
    size_t sb = ((size_t)(b * M_ + m)) * KSPLIT + part * (KSPLIT / 2);
    const float4* ps = (const float4*)(g_stPart + sb);
    float dot1 = 0.f, dot2 = 0.f, f0s = 0.f, sts = 0.f;
    #pragma unroll
    for (int i = 0; i < KSPLIT / 8; i++) {
        float4 v = p1[i];
        float4 w = p2[i];
        float4 x = pf[i];
        float4 y = ps[i];
        dot1 += (v.x + v.y) + (v.z + v.w);
        dot2 += (w.x + w.y) + (w.z + w.w);
        f0s  += (x.x + x.y) + (x.z + x.w);
        sts  += (y.x + y.y) + (y.z + y.w);
    }
    dot1 += __shfl_down_sync(0xffffffffu, dot1, 1);
    dot2 += __shfl_down_sync(0xffffffffu, dot2, 1);
    f0s  += __shfl_down_sync(0xffffffffu, f0s, 1);
    sts  += __shfl_down_sync(0xffffffffu, sts, 1);

    if (!valid || part) return;

    int cls = tcls[b * M_ + m];
    if (cls <= 0) { out[oid] = 100000.0f; return; }

    float Sp = g_Sp[b * N_ + n];
    float pos = Sp + sts;
    float cost_dice = 1.0f - 2.0f * dot1 / (pos + 0.001f);
    float cost_focal = (f0s + dot2) * (1.0f / (float)HW);
    float cost_class = -pred_prob[((size_t)b * C_ + cls) * N_ + n];

    const float* pmv = pred_mom + (size_t)(b * N_ + n) * 4;
    float p0 = __expf(fminf(pmv[0], 10.0f));
    float p1f = TWO_PI_F / (1.0f + __expf(-pmv[1]));
    float p2f = TWO_PI_F / (1.0f + __expf(-pmv[2]));
    float p3 = __expf(fminf(pmv[3], 10.0f));
    const float* tmv = tmom + (size_t)(b * M_ + m) * 4;
    float t0 = tmv[0], t1 = tmv[1], t2 = tmv[2], t3 = tmv[3];

    float pe = (t2 - p2f > PI_F) ? TWO_PI_F : 0.0f;
    float te = (p2f - t2 > PI_F) ? TWO_PI_F : 0.0f;
    float l1 = (fabsf(p0 / (t0 + 0.001f) - 1.0f)
              + fabsf(p1f / (t1 + 0.001f) - 1.0f)
              + fabsf((p2f + pe) / (t2 + te + 0.001f) - 1.0f)
              + fabsf(p3 / (t3 + 0.001f) - 1.0f)) * 0.25f;

    float w1 = p0, x1 = p1f, y1 = p2f, h1 = p3;
    float w2 = t0, x2 = t1, y2 = t2, h2 = t3;
    float y1e = (y2 - y1 > PI_F) ? TWO_PI_F : 0.0f;
    float y2e = (y1 - y2 > PI_F) ? TWO_PI_F : 0.0f;
    y1 += y1e;
    y2 += y2e;
    float r1 = x1 + w1 * 0.5f, l1b = x1 - w1 * 0.5f;
    float r2 = x2 + w2 * 0.5f, l2b = x2 - w2 * 0.5f;
    float u1 = y1 + h1 * 0.5f, d1 = y1 - h1 * 0.5f;
    float u2 = y2 + h2 * 0.5f, d2 = y2 - h2 * 0.5f;
    float w = fminf(r1, r2) - fmaxf(l1b, l2b);
    float h = fminf(u1, u2) - fmaxf(d1, d2);
    float iou = (w > 0.0f && h > 0.0f)
                ? (w * h) / (w1 * h1 + w2 * h2 - w * h + 0.001f) : 0.0f;
    float cw = fmaxf(r1, r2) - fminf(l1b, l2b);
    float ch = fmaxf(u1, u2) - fminf(d1, d2);
    float cw2 = cw * cw, ch2 = ch * ch;
    float dw = w1 - w2, dh = h1 - h2;
    float rho_w = dw * dw / (cw2 + 0.001f);
    float rho_h = dh * dh / (ch2 + 0.001f);
    float dx = x1 - x2, dy = y1 - y2;
    float rho_d = (dx * dx + dy * dy) / (cw2 + ch2 + 0.001f);
    float ce = 1.0f - iou + rho_d + rho_w + rho_h;

    out[oid] = 0.25f * cost_focal + 0.75f * cost_dice + cost_class
             + 0.8f * l1 + 0.2f * ce;
}

extern "C" void kernel_launch(void* const* d_in, const int* in_sizes, int n_in,
                              void* d_out, int out_size) {
    const float* pred_prob = (const float*)d_in[0];
    const float* pred_mask = (const float*)d_in[1];
    const float* pred_mom  = (const float*)d_in[2];
    const int*   tcls      = (const int*)d_in[3];
    const float* tmask     = (const float*)d_in[4];
    const float* tmom      = (const float*)d_in[5];
    float* out = (float*)d_out;

    static int configured = 0;
    if (!configured) {
        cudaFuncSetAttribute(k_dots, cudaFuncAttributeMaxDynamicSharedMemorySize,
                             DSMEM_BYTES);
        configured = 1;
    }

    k_sp<<<200, 256>>>(pred_mask);
    dim3 grid(KSPLIT, B_);
    k_dots<<<grid, 512, DSMEM_BYTES>>>(tmask, pred_mask);
    int total_threads = 2 * B_ * N_ * M_;
    k_assemble<<<(total_threads + 255) / 256, 256>>>(pred_prob, pred_mom, tcls, tmom, out);
}